// round 15
// baseline (speedup 1.0000x reference)
#include <cuda_runtime.h>

#define N_NODES 50000
#define N_EDGES 800000
#define HID 128
#define OUTC 10
#define N_LAYERS 3
#define N_GRAPHS 64
#define BN_EPS 1e-5f

#define BM 64
#define MLP_THREADS 256
#define MLP_GRID ((N_NODES + BM - 1) / BM)
#define MLP_SMEM ((2 * HID * HID + BM * HID) * (int)sizeof(float))

// ---------------- device scratch (static, allowed) ----------------
__device__ float d_h[(size_t)N_NODES * HID];    // agg base / h2 buffer
__device__ float d_xa[(size_t)N_NODES * HID];   // activation ping
__device__ float d_xb[(size_t)N_NODES * HID];   // activation pong
__device__ float d_g[N_GRAPHS * HID];           // pooled graph features
__device__ float d_bnsum[N_LAYERS * HID];
__device__ float d_bnsq[N_LAYERS * HID];

__device__ __forceinline__ void red_add_v4(float* addr, float4 v) {
    asm volatile("red.global.add.v4.f32 [%0], {%1, %2, %3, %4};"
                 :: "l"(addr), "f"(v.x), "f"(v.y), "f"(v.z), "f"(v.w)
                 : "memory");
}

// ---------------- init: h = x, zero stats + pool ----------------
__global__ void init_kernel(const float4* __restrict__ x) {
    int i = blockIdx.x * blockDim.x + threadIdx.x;   // grid covers exactly N_NODES*HID/4
    ((float4*)d_h)[i] = x[i];
    if (i < N_LAYERS * HID) { d_bnsum[i] = 0.f; d_bnsq[i] = 0.f; }
    if (i < N_GRAPHS * HID / 4) ((float4*)d_g)[i] = make_float4(0.f, 0.f, 0.f, 0.f);
}

// ---------------- edge scatter: h[dst] += x[src], one warp per edge ----------------
__global__ void scatter_kernel(const float4* __restrict__ x,
                               const int* __restrict__ src,
                               const int* __restrict__ dst) {
    int e = (blockIdx.x * blockDim.x + threadIdx.x) >> 5;
    int lane = threadIdx.x & 31;
    if (e >= N_EDGES) return;
    int s = __ldg(src + e);
    int d = __ldg(dst + e);
    float4 v = x[(size_t)s * (HID / 4) + lane];
    red_add_v4(d_h + (size_t)d * HID + lane * 4, v);
}

// ---------------- fused MLP: h := relu(h@W1+b1)@W2+b2, BN stats in epilogue ----------------
__global__ void __launch_bounds__(MLP_THREADS, 1)
mlp_kernel(const float* __restrict__ W1, const float* __restrict__ b1,
           const float* __restrict__ W2, const float* __restrict__ b2,
           int layer) {
    extern __shared__ float smem[];
    float* sW1 = smem;                 // [128][128]
    float* sW2 = smem + HID * HID;     // [128][128]
    float* sA  = smem + 2 * HID * HID; // [BM][128], reused for h1
    __shared__ float sSum[HID];
    __shared__ float sSq[HID];

    const int tid  = threadIdx.x;
    const int row0 = blockIdx.x * BM;

    #pragma unroll 4
    for (int i = tid; i < HID * HID / 4; i += MLP_THREADS) {
        ((float4*)sW1)[i] = ((const float4*)W1)[i];
        ((float4*)sW2)[i] = ((const float4*)W2)[i];
    }
    #pragma unroll 2
    for (int i = tid; i < BM * HID / 4; i += MLP_THREADS) {
        int r = i >> 5;
        int gr = row0 + r;
        float4 v = make_float4(0.f, 0.f, 0.f, 0.f);
        if (gr < N_NODES) v = ((const float4*)d_h)[(size_t)gr * (HID / 4) + (i & 31)];
        ((float4*)sA)[i] = v;
    }
    if (tid < HID) { sSum[tid] = 0.f; sSq[tid] = 0.f; }
    __syncthreads();

    const int ty = tid >> 4;
    const int tx = tid & 15;
    const int rbase = ty * 4;   // 4 rows per thread
    const int cbase = tx * 8;   // 8 cols per thread

    float acc[4][8];
    #pragma unroll
    for (int m = 0; m < 4; m++)
        #pragma unroll
        for (int n = 0; n < 8; n++) acc[m][n] = 0.f;

#define MLP_K_STEP(SW) do {                                                         \
        float a0 = sA[(rbase + 0) * HID + k];                                       \
        float a1 = sA[(rbase + 1) * HID + k];                                       \
        float a2 = sA[(rbase + 2) * HID + k];                                       \
        float a3 = sA[(rbase + 3) * HID + k];                                       \
        float4 w0 = *(const float4*)&(SW)[k * HID + cbase];                         \
        float4 w1 = *(const float4*)&(SW)[k * HID + cbase + 4];                     \
        acc[0][0] += a0 * w0.x; acc[0][1] += a0 * w0.y;                             \
        acc[0][2] += a0 * w0.z; acc[0][3] += a0 * w0.w;                             \
        acc[0][4] += a0 * w1.x; acc[0][5] += a0 * w1.y;                             \
        acc[0][6] += a0 * w1.z; acc[0][7] += a0 * w1.w;                             \
        acc[1][0] += a1 * w0.x; acc[1][1] += a1 * w0.y;                             \
        acc[1][2] += a1 * w0.z; acc[1][3] += a1 * w0.w;                             \
        acc[1][4] += a1 * w1.x; acc[1][5] += a1 * w1.y;                             \
        acc[1][6] += a1 * w1.z; acc[1][7] += a1 * w1.w;                             \
        acc[2][0] += a2 * w0.x; acc[2][1] += a2 * w0.y;                             \
        acc[2][2] += a2 * w0.z; acc[2][3] += a2 * w0.w;                             \
        acc[2][4] += a2 * w1.x; acc[2][5] += a2 * w1.y;                             \
        acc[2][6] += a2 * w1.z; acc[2][7] += a2 * w1.w;                             \
        acc[3][0] += a3 * w0.x; acc[3][1] += a3 * w0.y;                             \
        acc[3][2] += a3 * w0.z; acc[3][3] += a3 * w0.w;                             \
        acc[3][4] += a3 * w1.x; acc[3][5] += a3 * w1.y;                             \
        acc[3][6] += a3 * w1.z; acc[3][7] += a3 * w1.w;                             \
    } while (0)

    // ---- GEMM 1 ----
    #pragma unroll 8
    for (int k = 0; k < HID; k++) MLP_K_STEP(sW1);

    float bb[8];
    #pragma unroll
    for (int n = 0; n < 8; n++) bb[n] = __ldg(&b1[cbase + n]);

    __syncthreads();   // everyone done reading sA
    #pragma unroll
    for (int m = 0; m < 4; m++) {
        float4 v0, v1;
        v0.x = fmaxf(acc[m][0] + bb[0], 0.f);
        v0.y = fmaxf(acc[m][1] + bb[1], 0.f);
        v0.z = fmaxf(acc[m][2] + bb[2], 0.f);
        v0.w = fmaxf(acc[m][3] + bb[3], 0.f);
        v1.x = fmaxf(acc[m][4] + bb[4], 0.f);
        v1.y = fmaxf(acc[m][5] + bb[5], 0.f);
        v1.z = fmaxf(acc[m][6] + bb[6], 0.f);
        v1.w = fmaxf(acc[m][7] + bb[7], 0.f);
        *(float4*)&sA[(rbase + m) * HID + cbase]     = v0;
        *(float4*)&sA[(rbase + m) * HID + cbase + 4] = v1;
    }
    __syncthreads();

    // ---- GEMM 2 ----
    #pragma unroll
    for (int m = 0; m < 4; m++)
        #pragma unroll
        for (int n = 0; n < 8; n++) acc[m][n] = 0.f;

    #pragma unroll 8
    for (int k = 0; k < HID; k++) MLP_K_STEP(sW2);
#undef MLP_K_STEP

    #pragma unroll
    for (int n = 0; n < 8; n++) bb[n] = __ldg(&b2[cbase + n]);

    float cs[8], cq[8];
    #pragma unroll
    for (int n = 0; n < 8; n++) { cs[n] = 0.f; cq[n] = 0.f; }

    #pragma unroll
    for (int m = 0; m < 4; m++) {
        int gr = row0 + rbase + m;
        if (gr >= N_NODES) continue;
        float v[8];
        #pragma unroll
        for (int n = 0; n < 8; n++) {
            v[n] = acc[m][n] + bb[n];
            cs[n] += v[n];
            cq[n] += v[n] * v[n];
        }
        *(float4*)&d_h[(size_t)gr * HID + cbase]     = make_float4(v[0], v[1], v[2], v[3]);
        *(float4*)&d_h[(size_t)gr * HID + cbase + 4] = make_float4(v[4], v[5], v[6], v[7]);
    }
    #pragma unroll
    for (int n = 0; n < 8; n++) {
        atomicAdd(&sSum[cbase + n], cs[n]);
        atomicAdd(&sSq[cbase + n], cq[n]);
    }
    __syncthreads();
    if (tid < HID) {
        atomicAdd(&d_bnsum[layer * HID + tid], sSum[tid]);
        atomicAdd(&d_bnsq[layer * HID + tid], sSq[tid]);
    }
}

// ---------------- BN apply + ReLU; optionally refreshes h for next layer ----------------
__global__ void bn_apply_kernel(float* __restrict__ xout,
                                const float* __restrict__ gamma,
                                const float* __restrict__ beta,
                                int layer, int writeH) {
    __shared__ float sScale[HID], sShift[HID];
    if (threadIdx.x < HID) {
        int c = threadIdx.x;
        float mean = d_bnsum[layer * HID + c] * (1.f / N_NODES);
        float var  = d_bnsq[layer * HID + c] * (1.f / N_NODES) - mean * mean;
        float sc   = gamma[c] * rsqrtf(var + BN_EPS);
        sScale[c] = sc;
        sShift[c] = beta[c] - mean * sc;
    }
    __syncthreads();
    int i = blockIdx.x * blockDim.x + threadIdx.x;   // grid covers exactly N_NODES*HID/4
    int c4 = (i & 31) << 2;
    float4 v = ((float4*)d_h)[i];
    v.x = fmaxf(fmaf(v.x, sScale[c4 + 0], sShift[c4 + 0]), 0.f);
    v.y = fmaxf(fmaf(v.y, sScale[c4 + 1], sShift[c4 + 1]), 0.f);
    v.z = fmaxf(fmaf(v.z, sScale[c4 + 2], sShift[c4 + 2]), 0.f);
    v.w = fmaxf(fmaf(v.w, sScale[c4 + 3], sShift[c4 + 3]), 0.f);
    ((float4*)xout)[i] = v;
    if (writeH) ((float4*)d_h)[i] = v;
}

// ---------------- global_add_pool: sorted batch, run-length local accumulate ----------------
__global__ void pool_kernel(const float4* __restrict__ x, const int* __restrict__ batch) {
    int w = (blockIdx.x * blockDim.x + threadIdx.x) >> 5;
    int lane = threadIdx.x & 31;
    int start = w * 16;
    if (start >= N_NODES) return;
    int end = min(start + 16, N_NODES);
    int cur = __ldg(&batch[start]);
    float4 acc = make_float4(0.f, 0.f, 0.f, 0.f);
    for (int i = start; i < end; i++) {
        int b = __ldg(&batch[i]);
        if (b != cur) {
            red_add_v4(d_g + (size_t)cur * HID + lane * 4, acc);
            acc = make_float4(0.f, 0.f, 0.f, 0.f);
            cur = b;
        }
        float4 v = x[(size_t)i * (HID / 4) + lane];
        acc.x += v.x; acc.y += v.y; acc.z += v.z; acc.w += v.w;
    }
    red_add_v4(d_g + (size_t)cur * HID + lane * 4, acc);
}

// ---------------- final linear: out = g @ Wlin + blin ----------------
__global__ void final_kernel(const float* __restrict__ Wlin,
                             const float* __restrict__ blin,
                             float* __restrict__ out) {
    int tid = threadIdx.x;
    if (tid >= N_GRAPHS * OUTC) return;
    int gi = tid / OUTC;
    int o  = tid % OUTC;
    float s = __ldg(&blin[o]);
    const float* grow = d_g + gi * HID;
    #pragma unroll 16
    for (int k = 0; k < HID; k++)
        s = fmaf(grow[k], __ldg(&Wlin[k * OUTC + o]), s);
    out[gi * OUTC + o] = s;
}

// ---------------- launch ----------------
extern "C" void kernel_launch(void* const* d_in, const int* in_sizes, int n_in,
                              void* d_out, int out_size) {
    (void)in_sizes; (void)n_in; (void)out_size;
    const float* x0     = (const float*)d_in[0];
    const float* W1s    = (const float*)d_in[1];
    const float* b1s    = (const float*)d_in[2];
    const float* W2s    = (const float*)d_in[3];
    const float* b2s    = (const float*)d_in[4];
    const float* gammas = (const float*)d_in[5];
    const float* betas  = (const float*)d_in[6];
    const float* Wlin   = (const float*)d_in[7];
    const float* blin   = (const float*)d_in[8];
    const int*   ei     = (const int*)d_in[9];
    const int*   batch  = (const int*)d_in[10];
    const int* src = ei;
    const int* dst = ei + N_EDGES;
    float* out = (float*)d_out;

    float *xa, *xb;
    cudaGetSymbolAddress((void**)&xa, d_xa);
    cudaGetSymbolAddress((void**)&xb, d_xb);
    cudaFuncSetAttribute(mlp_kernel, cudaFuncAttributeMaxDynamicSharedMemorySize, MLP_SMEM);

    const int ELEM_BLOCKS = (N_NODES * HID / 4) / 256;   // 6250, exact
    const int SCAT_BLOCKS = (N_EDGES * 32) / 256;        // 100000, exact
    const int POOL_BLOCKS = (((N_NODES + 15) / 16) * 32 + 255) / 256;

    init_kernel<<<ELEM_BLOCKS, 256>>>((const float4*)x0);

    const float* xin = x0;
    float* bufs[3] = {xa, xb, xa};
    for (int l = 0; l < N_LAYERS; l++) {
        scatter_kernel<<<SCAT_BLOCKS, 256>>>((const float4*)xin, src, dst);
        mlp_kernel<<<MLP_GRID, MLP_THREADS, MLP_SMEM>>>(
            W1s + l * HID * HID, b1s + l * HID,
            W2s + l * HID * HID, b2s + l * HID, l);
        bn_apply_kernel<<<ELEM_BLOCKS, 256>>>(
            bufs[l], gammas + l * HID, betas + l * HID, l,
            (l < N_LAYERS - 1) ? 1 : 0);
        xin = bufs[l];
    }
    pool_kernel<<<POOL_BLOCKS, 256>>>((const float4*)xin, batch);
    final_kernel<<<1, N_GRAPHS * OUTC>>>(Wlin, blin, out);
}

// round 16
// speedup vs baseline: 1.2210x; 1.2210x over previous
#include <cuda_runtime.h>

#define N_NODES 50000
#define N_EDGES 800000
#define HID 128
#define OUTC 10
#define N_LAYERS 3
#define N_GRAPHS 64
#define BN_EPS 1e-5f

#define BM 64
#define MLP_THREADS 256
#define MLP_GRID ((N_NODES + BM - 1) / BM)
#define MLP_SMEM ((2 * HID * HID + BM * HID) * (int)sizeof(float))

typedef unsigned long long u64;

// ---------------- device scratch (static, allowed) ----------------
__device__ float d_h[(size_t)N_NODES * HID];    // MLP output (pre-BN)
__device__ float d_a[(size_t)N_NODES * HID];    // aggregated MLP input
__device__ float d_g[N_GRAPHS * HID];           // pooled graph features
__device__ float d_bnsum[N_LAYERS * HID];
__device__ float d_bnsq[N_LAYERS * HID];
__device__ float d_scale[HID];
__device__ float d_shift[HID];
__device__ int   d_deg[N_NODES];
__device__ int   d_off[N_NODES + 1];
__device__ int   d_pos[N_EDGES];
__device__ int   d_srcs[N_EDGES];

// ---------------- packed f32x2 helpers ----------------
__device__ __forceinline__ u64 pack_dup(float a) {
    u64 r;
    asm("mov.b64 %0, {%1, %1};" : "=l"(r) : "r"(__float_as_uint(a)));
    return r;
}
__device__ __forceinline__ void ffma2(u64& d, u64 a, u64 b) {
    asm("fma.rn.f32x2 %0, %1, %2, %0;" : "+l"(d) : "l"(a), "l"(b));
}
__device__ __forceinline__ float2 unpack2(u64 v) {
    unsigned lo, hi;
    asm("mov.b64 {%0, %1}, %2;" : "=r"(lo), "=r"(hi) : "l"(v));
    float2 r;
    r.x = __uint_as_float(lo);
    r.y = __uint_as_float(hi);
    return r;
}

__device__ __forceinline__ void red_add_v4(float* addr, float4 v) {
    asm volatile("red.global.add.v4.f32 [%0], {%1, %2, %3, %4};"
                 :: "l"(addr), "f"(v.x), "f"(v.y), "f"(v.z), "f"(v.w)
                 : "memory");
}

__device__ __forceinline__ float4 bnrelu4(float4 v, float4 sc, float4 sh) {
    v.x = fmaxf(fmaf(v.x, sc.x, sh.x), 0.f);
    v.y = fmaxf(fmaf(v.y, sc.y, sh.y), 0.f);
    v.z = fmaxf(fmaf(v.z, sc.z, sh.z), 0.f);
    v.w = fmaxf(fmaf(v.w, sc.w, sh.w), 0.f);
    return v;
}

// ---------------- prep: zero deg / stats / pool ----------------
__global__ void prep_zero_kernel() {
    int i = blockIdx.x * blockDim.x + threadIdx.x;
    if (i < N_NODES) d_deg[i] = 0;
    if (i < N_LAYERS * HID) { d_bnsum[i] = 0.f; d_bnsq[i] = 0.f; }
    if (i < N_GRAPHS * HID) d_g[i] = 0.f;
}

// ---------------- CSR build ----------------
__global__ void hist_kernel(const int* __restrict__ dst) {
    int e = blockIdx.x * blockDim.x + threadIdx.x;
    if (e < N_EDGES) d_pos[e] = atomicAdd(&d_deg[dst[e]], 1);
}

__global__ void scan_kernel() {
    __shared__ int sWarp[32];
    __shared__ int sCarry;
    const int tid = threadIdx.x;
    const int lane = tid & 31;
    const int wid = tid >> 5;
    if (tid == 0) sCarry = 0;
    __syncthreads();
    for (int base = 0; base < N_NODES; base += 1024) {
        int i = base + tid;
        int v = (i < N_NODES) ? d_deg[i] : 0;
        int x = v;
        #pragma unroll
        for (int o = 1; o < 32; o <<= 1) {
            int y = __shfl_up_sync(0xffffffffu, x, o);
            if (lane >= o) x += y;
        }
        if (lane == 31) sWarp[wid] = x;
        __syncthreads();
        if (wid == 0) {
            int s = sWarp[lane];
            #pragma unroll
            for (int o = 1; o < 32; o <<= 1) {
                int y = __shfl_up_sync(0xffffffffu, s, o);
                if (lane >= o) s += y;
            }
            sWarp[lane] = s;
        }
        __syncthreads();
        int add = sCarry + (wid > 0 ? sWarp[wid - 1] : 0);
        int incl = x + add;
        if (i < N_NODES) d_off[i + 1] = incl;
        int total = sCarry + sWarp[31];
        __syncthreads();
        if (tid == 0) sCarry = total;
        __syncthreads();
    }
    if (threadIdx.x == 0) d_off[0] = 0;
}

__global__ void csr_kernel(const int* __restrict__ src, const int* __restrict__ dst) {
    int e = blockIdx.x * blockDim.x + threadIdx.x;
    if (e < N_EDGES) d_srcs[d_off[dst[e]] + d_pos[e]] = src[e];
}

// ---------------- gather: d_a[n] = f(x[n]) + sum f(x[srcs]), f = bn+relu or identity ----------------
template<int BN>
__global__ void gather_kernel(const float4* __restrict__ xin) {
    int w = (blockIdx.x * blockDim.x + threadIdx.x) >> 5;
    int lane = threadIdx.x & 31;
    if (w >= N_NODES) return;
    float4 sc, sh;
    if (BN) {
        sc = ((const float4*)d_scale)[lane];
        sh = ((const float4*)d_shift)[lane];
    }
    float4 acc = xin[(size_t)w * 32 + lane];
    if (BN) acc = bnrelu4(acc, sc, sh);
    int beg = d_off[w], end = d_off[w + 1];
    for (int base = beg; base < end; base += 32) {
        int idx = 0;
        if (base + lane < end) idx = __ldg(&d_srcs[base + lane]);
        int cnt = min(32, end - base);
        #pragma unroll 4
        for (int t = 0; t < cnt; t++) {
            int s = __shfl_sync(0xffffffffu, idx, t);
            float4 v = xin[(size_t)s * 32 + lane];
            if (BN) v = bnrelu4(v, sc, sh);
            acc.x += v.x; acc.y += v.y; acc.z += v.z; acc.w += v.w;
        }
    }
    ((float4*)d_a)[(size_t)w * 32 + lane] = acc;
}

// ---------------- fused MLP (packed f32x2 FMA): d_h := relu(d_a@W1+b1)@W2+b2, BN stats ----------------
__global__ void __launch_bounds__(MLP_THREADS, 1)
mlp_kernel(const float* __restrict__ W1, const float* __restrict__ b1,
           const float* __restrict__ W2, const float* __restrict__ b2,
           int layer) {
    extern __shared__ float smem[];
    float* sW1 = smem;                 // [128][128]
    float* sW2 = smem + HID * HID;     // [128][128]
    float* sA  = smem + 2 * HID * HID; // [BM][128], reused for h1
    __shared__ float sSum[HID];
    __shared__ float sSq[HID];

    const int tid  = threadIdx.x;
    const int row0 = blockIdx.x * BM;

    #pragma unroll 4
    for (int i = tid; i < HID * HID / 4; i += MLP_THREADS) {
        ((float4*)sW1)[i] = ((const float4*)W1)[i];
        ((float4*)sW2)[i] = ((const float4*)W2)[i];
    }
    #pragma unroll 2
    for (int i = tid; i < BM * HID / 4; i += MLP_THREADS) {
        int r = i >> 5;
        int gr = row0 + r;
        float4 v = make_float4(0.f, 0.f, 0.f, 0.f);
        if (gr < N_NODES) v = ((const float4*)d_a)[(size_t)gr * (HID / 4) + (i & 31)];
        ((float4*)sA)[i] = v;
    }
    if (tid < HID) { sSum[tid] = 0.f; sSq[tid] = 0.f; }
    __syncthreads();

    const int ty = tid >> 4;
    const int tx = tid & 15;
    const int rbase = ty * 4;   // 4 rows per thread
    const int cbase = tx * 8;   // 8 cols per thread (4 f32x2 pairs)

    u64 acc[4][4];
    #pragma unroll
    for (int m = 0; m < 4; m++)
        #pragma unroll
        for (int j = 0; j < 4; j++) acc[m][j] = 0ull;

#define MLP_K_STEP(SW) do {                                                   \
        float a0 = sA[(rbase + 0) * HID + k];                                 \
        float a1 = sA[(rbase + 1) * HID + k];                                 \
        float a2 = sA[(rbase + 2) * HID + k];                                 \
        float a3 = sA[(rbase + 3) * HID + k];                                 \
        u64 A0 = pack_dup(a0), A1 = pack_dup(a1);                             \
        u64 A2 = pack_dup(a2), A3 = pack_dup(a3);                             \
        const u64* wp = (const u64*)&(SW)[k * HID + cbase];                   \
        u64 w0 = wp[0], w1 = wp[1], w2 = wp[2], w3 = wp[3];                   \
        ffma2(acc[0][0], A0, w0); ffma2(acc[0][1], A0, w1);                   \
        ffma2(acc[0][2], A0, w2); ffma2(acc[0][3], A0, w3);                   \
        ffma2(acc[1][0], A1, w0); ffma2(acc[1][1], A1, w1);                   \
        ffma2(acc[1][2], A1, w2); ffma2(acc[1][3], A1, w3);                   \
        ffma2(acc[2][0], A2, w0); ffma2(acc[2][1], A2, w1);                   \
        ffma2(acc[2][2], A2, w2); ffma2(acc[2][3], A2, w3);                   \
        ffma2(acc[3][0], A3, w0); ffma2(acc[3][1], A3, w1);                   \
        ffma2(acc[3][2], A3, w2); ffma2(acc[3][3], A3, w3);                   \
    } while (0)

    // ---- GEMM 1 ----
    #pragma unroll 8
    for (int k = 0; k < HID; k++) MLP_K_STEP(sW1);

    float bb[8];
    #pragma unroll
    for (int n = 0; n < 8; n++) bb[n] = __ldg(&b1[cbase + n]);

    __syncthreads();   // everyone done reading sA
    #pragma unroll
    for (int m = 0; m < 4; m++) {
        float v[8];
        #pragma unroll
        for (int j = 0; j < 4; j++) {
            float2 u = unpack2(acc[m][j]);
            v[2 * j + 0] = fmaxf(u.x + bb[2 * j + 0], 0.f);
            v[2 * j + 1] = fmaxf(u.y + bb[2 * j + 1], 0.f);
        }
        *(float4*)&sA[(rbase + m) * HID + cbase]     = make_float4(v[0], v[1], v[2], v[3]);
        *(float4*)&sA[(rbase + m) * HID + cbase + 4] = make_float4(v[4], v[5], v[6], v[7]);
    }
    __syncthreads();

    // ---- GEMM 2 ----
    #pragma unroll
    for (int m = 0; m < 4; m++)
        #pragma unroll
        for (int j = 0; j < 4; j++) acc[m][j] = 0ull;

    #pragma unroll 8
    for (int k = 0; k < HID; k++) MLP_K_STEP(sW2);
#undef MLP_K_STEP

    #pragma unroll
    for (int n = 0; n < 8; n++) bb[n] = __ldg(&b2[cbase + n]);

    float cs[8], cq[8];
    #pragma unroll
    for (int n = 0; n < 8; n++) { cs[n] = 0.f; cq[n] = 0.f; }

    #pragma unroll
    for (int m = 0; m < 4; m++) {
        int gr = row0 + rbase + m;
        if (gr >= N_NODES) continue;
        float v[8];
        #pragma unroll
        for (int j = 0; j < 4; j++) {
            float2 u = unpack2(acc[m][j]);
            v[2 * j + 0] = u.x + bb[2 * j + 0];
            v[2 * j + 1] = u.y + bb[2 * j + 1];
        }
        #pragma unroll
        for (int n = 0; n < 8; n++) {
            cs[n] += v[n];
            cq[n] += v[n] * v[n];
        }
        *(float4*)&d_h[(size_t)gr * HID + cbase]     = make_float4(v[0], v[1], v[2], v[3]);
        *(float4*)&d_h[(size_t)gr * HID + cbase + 4] = make_float4(v[4], v[5], v[6], v[7]);
    }
    #pragma unroll
    for (int n = 0; n < 8; n++) {
        atomicAdd(&sSum[cbase + n], cs[n]);
        atomicAdd(&sSq[cbase + n], cq[n]);
    }
    __syncthreads();
    if (tid < HID) {
        atomicAdd(&d_bnsum[layer * HID + tid], sSum[tid]);
        atomicAdd(&d_bnsq[layer * HID + tid], sSq[tid]);
    }
}

// ---------------- BN params from stats (tiny) ----------------
__global__ void bnparam_kernel(const float* __restrict__ gamma,
                               const float* __restrict__ beta, int layer) {
    int c = threadIdx.x;
    float mean = d_bnsum[layer * HID + c] * (1.f / N_NODES);
    float var  = d_bnsq[layer * HID + c] * (1.f / N_NODES) - mean * mean;
    float sc   = gamma[c] * rsqrtf(var + BN_EPS);
    d_scale[c] = sc;
    d_shift[c] = beta[c] - mean * sc;
}

// ---------------- global_add_pool over bn+relu(d_h) ----------------
__global__ void pool_kernel(const int* __restrict__ batch) {
    int w = (blockIdx.x * blockDim.x + threadIdx.x) >> 5;
    int lane = threadIdx.x & 31;
    int start = w * 16;
    if (start >= N_NODES) return;
    int end = min(start + 16, N_NODES);
    float4 sc = ((const float4*)d_scale)[lane];
    float4 sh = ((const float4*)d_shift)[lane];
    int cur = __ldg(&batch[start]);
    float4 acc = make_float4(0.f, 0.f, 0.f, 0.f);
    for (int i = start; i < end; i++) {
        int b = __ldg(&batch[i]);
        if (b != cur) {
            red_add_v4(d_g + (size_t)cur * HID + lane * 4, acc);
            acc = make_float4(0.f, 0.f, 0.f, 0.f);
            cur = b;
        }
        float4 v = ((const float4*)d_h)[(size_t)i * 32 + lane];
        v = bnrelu4(v, sc, sh);
        acc.x += v.x; acc.y += v.y; acc.z += v.z; acc.w += v.w;
    }
    red_add_v4(d_g + (size_t)cur * HID + lane * 4, acc);
}

// ---------------- final linear: out = g @ Wlin + blin ----------------
__global__ void final_kernel(const float* __restrict__ Wlin,
                             const float* __restrict__ blin,
                             float* __restrict__ out) {
    int tid = threadIdx.x;
    if (tid >= N_GRAPHS * OUTC) return;
    int gi = tid / OUTC;
    int o  = tid % OUTC;
    float s = __ldg(&blin[o]);
    const float* grow = d_g + gi * HID;
    #pragma unroll 16
    for (int k = 0; k < HID; k++)
        s = fmaf(grow[k], __ldg(&Wlin[k * OUTC + o]), s);
    out[gi * OUTC + o] = s;
}

// ---------------- launch ----------------
extern "C" void kernel_launch(void* const* d_in, const int* in_sizes, int n_in,
                              void* d_out, int out_size) {
    (void)in_sizes; (void)n_in; (void)out_size;
    const float* x0     = (const float*)d_in[0];
    const float* W1s    = (const float*)d_in[1];
    const float* b1s    = (const float*)d_in[2];
    const float* W2s    = (const float*)d_in[3];
    const float* b2s    = (const float*)d_in[4];
    const float* gammas = (const float*)d_in[5];
    const float* betas  = (const float*)d_in[6];
    const float* Wlin   = (const float*)d_in[7];
    const float* blin   = (const float*)d_in[8];
    const int*   ei     = (const int*)d_in[9];
    const int*   batch  = (const int*)d_in[10];
    const int* src = ei;
    const int* dst = ei + N_EDGES;
    float* out = (float*)d_out;

    float* hptr;
    cudaGetSymbolAddress((void**)&hptr, d_h);
    cudaFuncSetAttribute(mlp_kernel, cudaFuncAttributeMaxDynamicSharedMemorySize, MLP_SMEM);

    const int ZERO_BLOCKS   = (N_NODES + 255) / 256;          // covers deg/stats/g
    const int EDGE_BLOCKS   = (N_EDGES + 255) / 256;          // 3125
    const int GATHER_BLOCKS = (N_NODES * 32 + 255) / 256;     // 6250
    const int POOL_BLOCKS   = (((N_NODES + 15) / 16) * 32 + 255) / 256;

    // CSR build + zeroing (once per launch)
    prep_zero_kernel<<<ZERO_BLOCKS, 256>>>();
    hist_kernel<<<EDGE_BLOCKS, 256>>>(dst);
    scan_kernel<<<1, 1024>>>();
    csr_kernel<<<EDGE_BLOCKS, 256>>>(src, dst);

    for (int l = 0; l < N_LAYERS; l++) {
        if (l == 0)
            gather_kernel<0><<<GATHER_BLOCKS, 256>>>((const float4*)x0);
        else
            gather_kernel<1><<<GATHER_BLOCKS, 256>>>((const float4*)hptr);
        mlp_kernel<<<MLP_GRID, MLP_THREADS, MLP_SMEM>>>(
            W1s + l * HID * HID, b1s + l * HID,
            W2s + l * HID * HID, b2s + l * HID, l);
        bnparam_kernel<<<1, HID>>>(gammas + l * HID, betas + l * HID, l);
    }
    pool_kernel<<<POOL_BLOCKS, 256>>>(batch);
    final_kernel<<<1, N_GRAPHS * OUTC>>>(Wlin, blin, out);
}

// round 17
// speedup vs baseline: 1.2706x; 1.0406x over previous
#include <cuda_runtime.h>

#define N_NODES 50000
#define N_EDGES 800000
#define HID 128
#define OUTC 10
#define N_LAYERS 3
#define N_GRAPHS 64
#define BN_EPS 1e-5f

#define BM 128
#define MLP_THREADS 512
#define MLP_GRID ((N_NODES + BM - 1) / BM)
// sA [BM][HID] + sW [HID][HID], staged one weight matrix at a time
#define MLP_SMEM ((HID * HID + BM * HID) * (int)sizeof(float))

typedef unsigned long long u64;

// ---------------- device scratch (static, allowed) ----------------
__device__ float d_h[(size_t)N_NODES * HID];    // MLP output (pre-BN)
__device__ float d_a[(size_t)N_NODES * HID];    // aggregated MLP input
__device__ float d_g[N_GRAPHS * HID];           // pooled graph features
__device__ float d_bnsum[N_LAYERS * HID];
__device__ float d_bnsq[N_LAYERS * HID];
__device__ float d_scale[HID];
__device__ float d_shift[HID];
__device__ int   d_deg[N_NODES];
__device__ int   d_off[N_NODES + 1];
__device__ int   d_pos[N_EDGES];
__device__ int   d_srcs[N_EDGES];

// ---------------- packed f32x2 helpers ----------------
__device__ __forceinline__ u64 pack_dup(float a) {
    u64 r;
    asm("mov.b64 %0, {%1, %1};" : "=l"(r) : "r"(__float_as_uint(a)));
    return r;
}
__device__ __forceinline__ void ffma2(u64& d, u64 a, u64 b) {
    asm("fma.rn.f32x2 %0, %1, %2, %0;" : "+l"(d) : "l"(a), "l"(b));
}
__device__ __forceinline__ float2 unpack2(u64 v) {
    unsigned lo, hi;
    asm("mov.b64 {%0, %1}, %2;" : "=r"(lo), "=r"(hi) : "l"(v));
    float2 r;
    r.x = __uint_as_float(lo);
    r.y = __uint_as_float(hi);
    return r;
}

__device__ __forceinline__ void red_add_v4(float* addr, float4 v) {
    asm volatile("red.global.add.v4.f32 [%0], {%1, %2, %3, %4};"
                 :: "l"(addr), "f"(v.x), "f"(v.y), "f"(v.z), "f"(v.w)
                 : "memory");
}

__device__ __forceinline__ float4 bnrelu4(float4 v, float4 sc, float4 sh) {
    v.x = fmaxf(fmaf(v.x, sc.x, sh.x), 0.f);
    v.y = fmaxf(fmaf(v.y, sc.y, sh.y), 0.f);
    v.z = fmaxf(fmaf(v.z, sc.z, sh.z), 0.f);
    v.w = fmaxf(fmaf(v.w, sc.w, sh.w), 0.f);
    return v;
}

// ---------------- prep: zero deg / stats / pool ----------------
__global__ void prep_zero_kernel() {
    int i = blockIdx.x * blockDim.x + threadIdx.x;
    if (i < N_NODES) d_deg[i] = 0;
    if (i < N_LAYERS * HID) { d_bnsum[i] = 0.f; d_bnsq[i] = 0.f; }
    if (i < N_GRAPHS * HID) d_g[i] = 0.f;
}

// ---------------- CSR build (4 edges / thread for MLP) ----------------
__global__ void hist_kernel(const int4* __restrict__ dst4) {
    int t = blockIdx.x * blockDim.x + threadIdx.x;
    if (t >= N_EDGES / 4) return;
    int4 d = __ldg(&dst4[t]);
    int e = t * 4;
    int p0 = atomicAdd(&d_deg[d.x], 1);
    int p1 = atomicAdd(&d_deg[d.y], 1);
    int p2 = atomicAdd(&d_deg[d.z], 1);
    int p3 = atomicAdd(&d_deg[d.w], 1);
    d_pos[e + 0] = p0; d_pos[e + 1] = p1;
    d_pos[e + 2] = p2; d_pos[e + 3] = p3;
}

__global__ void scan_kernel() {
    __shared__ int sWarp[32];
    __shared__ int sCarry;
    const int tid = threadIdx.x;
    const int lane = tid & 31;
    const int wid = tid >> 5;
    if (tid == 0) sCarry = 0;
    __syncthreads();
    for (int base = 0; base < N_NODES; base += 1024) {
        int i = base + tid;
        int v = (i < N_NODES) ? d_deg[i] : 0;
        int x = v;
        #pragma unroll
        for (int o = 1; o < 32; o <<= 1) {
            int y = __shfl_up_sync(0xffffffffu, x, o);
            if (lane >= o) x += y;
        }
        if (lane == 31) sWarp[wid] = x;
        __syncthreads();
        if (wid == 0) {
            int s = sWarp[lane];
            #pragma unroll
            for (int o = 1; o < 32; o <<= 1) {
                int y = __shfl_up_sync(0xffffffffu, s, o);
                if (lane >= o) s += y;
            }
            sWarp[lane] = s;
        }
        __syncthreads();
        int add = sCarry + (wid > 0 ? sWarp[wid - 1] : 0);
        int incl = x + add;
        if (i < N_NODES) d_off[i + 1] = incl;
        int total = sCarry + sWarp[31];
        __syncthreads();
        if (tid == 0) sCarry = total;
        __syncthreads();
    }
    if (threadIdx.x == 0) d_off[0] = 0;
}

__global__ void csr_kernel(const int4* __restrict__ src4, const int4* __restrict__ dst4) {
    int t = blockIdx.x * blockDim.x + threadIdx.x;
    if (t >= N_EDGES / 4) return;
    int4 s = __ldg(&src4[t]);
    int4 d = __ldg(&dst4[t]);
    int e = t * 4;
    int4 p = *(const int4*)&d_pos[e];
    d_srcs[d_off[d.x] + p.x] = s.x;
    d_srcs[d_off[d.y] + p.y] = s.y;
    d_srcs[d_off[d.z] + p.z] = s.z;
    d_srcs[d_off[d.w] + p.w] = s.w;
}

// ---------------- gather: d_a[n] = f(x[n]) + sum f(x[srcs]), f = bn+relu or identity ----------------
template<int BN>
__global__ void gather_kernel(const float4* __restrict__ xin) {
    int w = (blockIdx.x * blockDim.x + threadIdx.x) >> 5;
    int lane = threadIdx.x & 31;
    if (w >= N_NODES) return;
    float4 sc, sh;
    if (BN) {
        sc = ((const float4*)d_scale)[lane];
        sh = ((const float4*)d_shift)[lane];
    }
    float4 acc = xin[(size_t)w * 32 + lane];
    if (BN) acc = bnrelu4(acc, sc, sh);
    float4 acc2 = make_float4(0.f, 0.f, 0.f, 0.f);
    int beg = d_off[w], end = d_off[w + 1];
    for (int base = beg; base < end; base += 32) {
        int idx = 0;
        if (base + lane < end) idx = __ldg(&d_srcs[base + lane]);
        int cnt = min(32, end - base);
        int t = 0;
        #pragma unroll 4
        for (; t + 2 <= cnt; t += 2) {
            int s0 = __shfl_sync(0xffffffffu, idx, t);
            int s1 = __shfl_sync(0xffffffffu, idx, t + 1);
            float4 v0 = xin[(size_t)s0 * 32 + lane];
            float4 v1 = xin[(size_t)s1 * 32 + lane];
            if (BN) { v0 = bnrelu4(v0, sc, sh); v1 = bnrelu4(v1, sc, sh); }
            acc.x += v0.x; acc.y += v0.y; acc.z += v0.z; acc.w += v0.w;
            acc2.x += v1.x; acc2.y += v1.y; acc2.z += v1.z; acc2.w += v1.w;
        }
        if (t < cnt) {
            int s0 = __shfl_sync(0xffffffffu, idx, t);
            float4 v0 = xin[(size_t)s0 * 32 + lane];
            if (BN) v0 = bnrelu4(v0, sc, sh);
            acc.x += v0.x; acc.y += v0.y; acc.z += v0.z; acc.w += v0.w;
        }
    }
    acc.x += acc2.x; acc.y += acc2.y; acc.z += acc2.z; acc.w += acc2.w;
    ((float4*)d_a)[(size_t)w * 32 + lane] = acc;
}

// ---------------- fused MLP (packed f32x2 FMA): d_h := relu(d_a@W1+b1)@W2+b2, BN stats ----------------
__global__ void __launch_bounds__(MLP_THREADS, 1)
mlp_kernel(const float* __restrict__ W1, const float* __restrict__ b1,
           const float* __restrict__ W2, const float* __restrict__ b2,
           int layer) {
    extern __shared__ float smem[];
    float* sW = smem;                  // [128][128], staged W1 then W2
    float* sA = smem + HID * HID;      // [BM][128], reused for h1
    __shared__ float sSum[HID];
    __shared__ float sSq[HID];

    const int tid  = threadIdx.x;
    const int row0 = blockIdx.x * BM;

    // stage W1 + A tile
    #pragma unroll 8
    for (int i = tid; i < HID * HID / 4; i += MLP_THREADS)
        ((float4*)sW)[i] = ((const float4*)W1)[i];
    #pragma unroll 8
    for (int i = tid; i < BM * HID / 4; i += MLP_THREADS) {
        int r = i >> 5;
        int gr = row0 + r;
        float4 v = make_float4(0.f, 0.f, 0.f, 0.f);
        if (gr < N_NODES) v = ((const float4*)d_a)[(size_t)gr * (HID / 4) + (i & 31)];
        ((float4*)sA)[i] = v;
    }
    if (tid < HID) { sSum[tid] = 0.f; sSq[tid] = 0.f; }
    __syncthreads();

    const int ty = tid >> 4;        // 0..31
    const int tx = tid & 15;        // 0..15
    const int rbase = ty * 4;       // 4 rows per thread  (32*4 = 128)
    const int cbase = tx * 8;       // 8 cols per thread  (4 f32x2 pairs)

    u64 acc[4][4];
    #pragma unroll
    for (int m = 0; m < 4; m++)
        #pragma unroll
        for (int j = 0; j < 4; j++) acc[m][j] = 0ull;

#define MLP_K_STEP do {                                                       \
        float a0 = sA[(rbase + 0) * HID + k];                                 \
        float a1 = sA[(rbase + 1) * HID + k];                                 \
        float a2 = sA[(rbase + 2) * HID + k];                                 \
        float a3 = sA[(rbase + 3) * HID + k];                                 \
        u64 A0 = pack_dup(a0), A1 = pack_dup(a1);                             \
        u64 A2 = pack_dup(a2), A3 = pack_dup(a3);                             \
        const u64* wp = (const u64*)&sW[k * HID + cbase];                     \
        u64 w0 = wp[0], w1 = wp[1], w2 = wp[2], w3 = wp[3];                   \
        ffma2(acc[0][0], A0, w0); ffma2(acc[0][1], A0, w1);                   \
        ffma2(acc[0][2], A0, w2); ffma2(acc[0][3], A0, w3);                   \
        ffma2(acc[1][0], A1, w0); ffma2(acc[1][1], A1, w1);                   \
        ffma2(acc[1][2], A1, w2); ffma2(acc[1][3], A1, w3);                   \
        ffma2(acc[2][0], A2, w0); ffma2(acc[2][1], A2, w1);                   \
        ffma2(acc[2][2], A2, w2); ffma2(acc[2][3], A2, w3);                   \
        ffma2(acc[3][0], A3, w0); ffma2(acc[3][1], A3, w1);                   \
        ffma2(acc[3][2], A3, w2); ffma2(acc[3][3], A3, w3);                   \
    } while (0)

    // ---- GEMM 1 ----
    #pragma unroll 8
    for (int k = 0; k < HID; k++) MLP_K_STEP;

    float bb[8];
    #pragma unroll
    for (int n = 0; n < 8; n++) bb[n] = __ldg(&b1[cbase + n]);

    __syncthreads();   // all GEMM1 reads of sA/sW done

    // write h1 into sA, stage W2 into sW
    #pragma unroll
    for (int m = 0; m < 4; m++) {
        float v[8];
        #pragma unroll
        for (int j = 0; j < 4; j++) {
            float2 u = unpack2(acc[m][j]);
            v[2 * j + 0] = fmaxf(u.x + bb[2 * j + 0], 0.f);
            v[2 * j + 1] = fmaxf(u.y + bb[2 * j + 1], 0.f);
        }
        *(float4*)&sA[(rbase + m) * HID + cbase]     = make_float4(v[0], v[1], v[2], v[3]);
        *(float4*)&sA[(rbase + m) * HID + cbase + 4] = make_float4(v[4], v[5], v[6], v[7]);
    }
    #pragma unroll 8
    for (int i = tid; i < HID * HID / 4; i += MLP_THREADS)
        ((float4*)sW)[i] = ((const float4*)W2)[i];
    __syncthreads();

    // ---- GEMM 2 ----
    #pragma unroll
    for (int m = 0; m < 4; m++)
        #pragma unroll
        for (int j = 0; j < 4; j++) acc[m][j] = 0ull;

    #pragma unroll 8
    for (int k = 0; k < HID; k++) MLP_K_STEP;
#undef MLP_K_STEP

    #pragma unroll
    for (int n = 0; n < 8; n++) bb[n] = __ldg(&b2[cbase + n]);

    float cs[8], cq[8];
    #pragma unroll
    for (int n = 0; n < 8; n++) { cs[n] = 0.f; cq[n] = 0.f; }

    #pragma unroll
    for (int m = 0; m < 4; m++) {
        int gr = row0 + rbase + m;
        if (gr >= N_NODES) continue;
        float v[8];
        #pragma unroll
        for (int j = 0; j < 4; j++) {
            float2 u = unpack2(acc[m][j]);
            v[2 * j + 0] = u.x + bb[2 * j + 0];
            v[2 * j + 1] = u.y + bb[2 * j + 1];
        }
        #pragma unroll
        for (int n = 0; n < 8; n++) {
            cs[n] += v[n];
            cq[n] += v[n] * v[n];
        }
        *(float4*)&d_h[(size_t)gr * HID + cbase]     = make_float4(v[0], v[1], v[2], v[3]);
        *(float4*)&d_h[(size_t)gr * HID + cbase + 4] = make_float4(v[4], v[5], v[6], v[7]);
    }
    #pragma unroll
    for (int n = 0; n < 8; n++) {
        atomicAdd(&sSum[cbase + n], cs[n]);
        atomicAdd(&sSq[cbase + n], cq[n]);
    }
    __syncthreads();
    if (tid < HID) {
        atomicAdd(&d_bnsum[layer * HID + tid], sSum[tid]);
        atomicAdd(&d_bnsq[layer * HID + tid], sSq[tid]);
    }
}

// ---------------- BN params from stats (tiny) ----------------
__global__ void bnparam_kernel(const float* __restrict__ gamma,
                               const float* __restrict__ beta, int layer) {
    int c = threadIdx.x;
    float mean = d_bnsum[layer * HID + c] * (1.f / N_NODES);
    float var  = d_bnsq[layer * HID + c] * (1.f / N_NODES) - mean * mean;
    float sc   = gamma[c] * rsqrtf(var + BN_EPS);
    d_scale[c] = sc;
    d_shift[c] = beta[c] - mean * sc;
}

// ---------------- global_add_pool over bn+relu(d_h) ----------------
__global__ void pool_kernel(const int* __restrict__ batch) {
    int w = (blockIdx.x * blockDim.x + threadIdx.x) >> 5;
    int lane = threadIdx.x & 31;
    int start = w * 16;
    if (start >= N_NODES) return;
    int end = min(start + 16, N_NODES);
    float4 sc = ((const float4*)d_scale)[lane];
    float4 sh = ((const float4*)d_shift)[lane];
    int cur = __ldg(&batch[start]);
    float4 acc = make_float4(0.f, 0.f, 0.f, 0.f);
    for (int i = start; i < end; i++) {
        int b = __ldg(&batch[i]);
        if (b != cur) {
            red_add_v4(d_g + (size_t)cur * HID + lane * 4, acc);
            acc = make_float4(0.f, 0.f, 0.f, 0.f);
            cur = b;
        }
        float4 v = ((const float4*)d_h)[(size_t)i * 32 + lane];
        v = bnrelu4(v, sc, sh);
        acc.x += v.x; acc.y += v.y; acc.z += v.z; acc.w += v.w;
    }
    red_add_v4(d_g + (size_t)cur * HID + lane * 4, acc);
}

// ---------------- final linear: out = g @ Wlin + blin ----------------
__global__ void final_kernel(const float* __restrict__ Wlin,
                             const float* __restrict__ blin,
                             float* __restrict__ out) {
    int tid = threadIdx.x;
    if (tid >= N_GRAPHS * OUTC) return;
    int gi = tid / OUTC;
    int o  = tid % OUTC;
    float s = __ldg(&blin[o]);
    const float* grow = d_g + gi * HID;
    #pragma unroll 16
    for (int k = 0; k < HID; k++)
        s = fmaf(grow[k], __ldg(&Wlin[k * OUTC + o]), s);
    out[gi * OUTC + o] = s;
}

// ---------------- launch ----------------
extern "C" void kernel_launch(void* const* d_in, const int* in_sizes, int n_in,
                              void* d_out, int out_size) {
    (void)in_sizes; (void)n_in; (void)out_size;
    const float* x0     = (const float*)d_in[0];
    const float* W1s    = (const float*)d_in[1];
    const float* b1s    = (const float*)d_in[2];
    const float* W2s    = (const float*)d_in[3];
    const float* b2s    = (const float*)d_in[4];
    const float* gammas = (const float*)d_in[5];
    const float* betas  = (const float*)d_in[6];
    const float* Wlin   = (const float*)d_in[7];
    const float* blin   = (const float*)d_in[8];
    const int*   ei     = (const int*)d_in[9];
    const int*   batch  = (const int*)d_in[10];
    const int* src = ei;
    const int* dst = ei + N_EDGES;
    float* out = (float*)d_out;

    float* hptr;
    cudaGetSymbolAddress((void**)&hptr, d_h);
    cudaFuncSetAttribute(mlp_kernel, cudaFuncAttributeMaxDynamicSharedMemorySize, MLP_SMEM);

    const int ZERO_BLOCKS   = (N_NODES + 255) / 256;
    const int EDGE4_BLOCKS  = (N_EDGES / 4 + 255) / 256;
    const int GATHER_BLOCKS = (N_NODES * 32 + 255) / 256;
    const int POOL_BLOCKS   = (((N_NODES + 15) / 16) * 32 + 255) / 256;

    // CSR build + zeroing (once per launch)
    prep_zero_kernel<<<ZERO_BLOCKS, 256>>>();
    hist_kernel<<<EDGE4_BLOCKS, 256>>>((const int4*)dst);
    scan_kernel<<<1, 1024>>>();
    csr_kernel<<<EDGE4_BLOCKS, 256>>>((const int4*)src, (const int4*)dst);

    for (int l = 0; l < N_LAYERS; l++) {
        if (l == 0)
            gather_kernel<0><<<GATHER_BLOCKS, 256>>>((const float4*)x0);
        else
            gather_kernel<1><<<GATHER_BLOCKS, 256>>>((const float4*)hptr);
        mlp_kernel<<<MLP_GRID, MLP_THREADS, MLP_SMEM>>>(
            W1s + l * HID * HID, b1s + l * HID,
            W2s + l * HID * HID, b2s + l * HID, l);
        bnparam_kernel<<<1, HID>>>(gammas + l * HID, betas + l * HID, l);
    }
    pool_kernel<<<POOL_BLOCKS, 256>>>(batch);
    final_kernel<<<1, N_GRAPHS * OUTC>>>(Wlin, blin, out);
}